// round 6
// baseline (speedup 1.0000x reference)
#include <cuda_runtime.h>
#include <cuda_fp16.h>
#include <cstdint>

#define NPATH 13
#define SMEM_SZ 69632

// ---------------- static device scratch ----------------
__device__ __align__(256) float g_cg[573];
__device__ __align__(256) __half2 g_W[3*128*640];        // B[n][k] = (h,h), 640-col padded

__device__ const int c_L1[NPATH]   = {0,0,0,1,1,1,1,1,2,2,2,2,2};
__device__ const int c_L2[NPATH]   = {0,1,2,0,1,1,2,3,0,1,2,2,3};
__device__ const int c_LO[NPATH]   = {0,1,2,1,0,2,1,2,2,1,0,2,1};
__device__ const int c_CGOFF[NPATH]= {0,1,10,35,44,53,98,143,248,273,318,343,468};
__device__ const int c_PB[3][5] = {
  {0,      65536,  163840, 0,      0     },
  {16384,  49152,  98304,  147456, 196608},
  {32768,  81920,  114688, 131072, 180224}
};

// fused-kernel tables
__device__ const int g_sub_g[9]  = {0,1,1,1,2,2,2,2,2};
__device__ const int g_sub_kq[9] = {0,0,1,2,0,1,2,3,4};
__device__ const int gP[3]      = {3,5,5};
__device__ const int gNI[3]     = {9,17,17};
__device__ const int gC[3]      = {12,20,20};     // K-chunks of 32 cols
__device__ const int gnk[3]     = {1,3,5};
__device__ const int gobase[3]  = {0,128,512};
__device__ const int gl1[3][5]  = {{0,1,2,0,0},{0,1,1,2,2},{0,1,1,2,2}};
__device__ const int gl2[3][5]  = {{0,1,2,0,0},{1,0,2,1,3},{2,1,3,0,2}};
__device__ const int gcgo[3][5] = {{0,44,318,0,0},{1,35,98,273,468},{10,53,143,248,343}};
__device__ const int gmvo[3][5] = {{0,1,4,0,0},{0,1,4,7,12},{0,1,4,7,12}};
__device__ const int c_xoff[3]  = {0,128,512};
__device__ const int c_yoff[4]  = {0,1,4,9};

// ---------------- CG computation (fp64, ported from reference) ----------------
__device__ double dfact(int n){ double r = 1.0; for (int i = 2; i <= n; ++i) r *= (double)i; return r; }

__device__ double su2_cg(int j1,int m1,int j2,int m2,int j3,int m3){
  if (m3 != m1 + m2) return 0.0;
  int vmin = max(max(-j1 + j2 + m3, -j1 + m1), 0);
  int vmax = min(min(j2 + j3 + m1, j3 - j1 + j2), j3 + m3);
  double C = sqrt((double)(2*j3+1) * dfact(j3+j1-j2) * dfact(j3-j1+j2) * dfact(j1+j2-j3)
                  * dfact(j3+m3) * dfact(j3-m3)
                  / (dfact(j1+j2+j3+1) * dfact(j1-m1) * dfact(j1+m1) * dfact(j2-m2) * dfact(j2+m2)));
  double S = 0.0;
  for (int v = vmin; v <= vmax; ++v){
    double sg = ((v + j2 + m2) & 1) ? -1.0 : 1.0;
    S += sg * dfact(j2+j3+m1-v) * dfact(j1-m1+v)
         / (dfact(v) * dfact(j3-j1+j2-v) * dfact(j3+m3-v) * dfact(v+j1-j2-m3));
  }
  return C * S;
}

__device__ void build_q(int l, double (*qr)[7], double (*qi)[7]){
  for (int a = 0; a < 7; ++a) for (int b = 0; b < 7; ++b){ qr[a][b] = 0.0; qi[a][b] = 0.0; }
  double s = 1.0 / sqrt(2.0);
  for (int m = -l; m < 0; ++m){ qr[l+m][l-m] = s; qi[l+m][l+m] = -s; }
  qr[l][l] = 1.0;
  for (int m = 1; m <= l; ++m){
    double sg = (m & 1) ? -1.0 : 1.0;
    qr[l+m][l+m] = sg * s; qi[l+m][l-m] = sg * s;
  }
  int ph = l & 3;
  if (ph){
    for (int a = 0; a < 2*l+1; ++a) for (int b = 0; b < 2*l+1; ++b){
      double re = qr[a][b], im = qi[a][b];
      if (ph == 1){ qr[a][b] =  im; qi[a][b] = -re; }
      else if (ph == 2){ qr[a][b] = -re; qi[a][b] = -im; }
      else { qr[a][b] = -im; qi[a][b] =  re; }
    }
  }
}

__global__ void cg_kernel(){
  int p = threadIdx.x;
  if (p >= NPATH) return;
  int l1 = c_L1[p], l2 = c_L2[p], l3 = c_LO[p];
  int d1 = 2*l1+1, d2 = 2*l2+1, d3 = 2*l3+1;

  double Ccg[5][7][5];
  for (int a = 0; a < 5; ++a) for (int b = 0; b < 7; ++b) for (int c = 0; c < 5; ++c) Ccg[a][b][c] = 0.0;
  for (int m1 = -l1; m1 <= l1; ++m1)
    for (int m2 = -l2; m2 <= l2; ++m2){
      int m3 = m1 + m2;
      if (m3 >= -l3 && m3 <= l3)
        Ccg[l1+m1][l2+m2][l3+m3] = su2_cg(l1, m1, l2, m2, l3, m3);
    }

  double q1r[7][7], q1i[7][7], q2r[7][7], q2i[7][7], q3r[7][7], q3i[7][7];
  build_q(l1, q1r, q1i); build_q(l2, q2r, q2i); build_q(l3, q3r, q3i);

  double outv[5][7][5];
  double norm2 = 0.0;
  for (int j = 0; j < d1; ++j)
    for (int l = 0; l < d2; ++l)
      for (int m = 0; m < d3; ++m){
        double re = 0.0;
        for (int i = 0; i < d1; ++i){
          double a1r = q1r[i][j], a1i = q1i[i][j];
          if (a1r == 0.0 && a1i == 0.0) continue;
          for (int k = 0; k < d2; ++k){
            double a2r = q2r[k][l], a2i = q2i[k][l];
            if (a2r == 0.0 && a2i == 0.0) continue;
            double ar = a1r*a2r - a1i*a2i;
            double ai = a1r*a2i + a1i*a2r;
            for (int n = 0; n < d3; ++n){
              double c = Ccg[i][k][n];
              if (c == 0.0) continue;
              re += c * (ar*q3r[n][m] - ai*(-q3i[n][m]));
            }
          }
        }
        outv[j][l][m] = re;
        norm2 += re * re;
      }
  double cio = (l3 == 0) ? sqrt(1.0/384.0) : (l3 == 1 ? sqrt(3.0/640.0) : sqrt(5.0/640.0));
  double inv = cio / sqrt(norm2);
  for (int j = 0; j < d1; ++j)
    for (int l = 0; l < d2; ++l)
      for (int m = 0; m < d3; ++m)
        g_cg[c_CGOFF[p] + (j*d2 + l)*d3 + m] = (float)(outv[j][l][m] * inv);
}

// ---------------- weight prep: B[n][k] = (h, h) ----------------
__global__ void wprep(const float* __restrict__ w){
  int idx = blockIdx.x * 256 + threadIdx.x;
  if (idx >= 3*128*640) return;
  int g = idx / (128*640);
  int rem = idx - g*128*640;
  int n = rem / 640, k = rem % 640;
  int K = (g == 0) ? 384 : 640;
  float v = 0.f;
  if (k < K) v = w[c_PB[g][k >> 7] + (k & 127)*128 + n];
  __half h = __float2half_rn(v);
  g_W[idx] = __halves2half2(h, h);
}

// ---------------- fused GEMM ----------------
__device__ __forceinline__ uint32_t smem_u32(const void* p){
  uint32_t a;
  asm("{ .reg .u64 t; cvta.to.shared.u64 t, %1; cvt.u32.u64 %0, t; }" : "=r"(a) : "l"(p));
  return a;
}
#define SWZ(off) ((off) ^ (((off) >> 3) & 0x70))

__device__ __forceinline__ void cp16(uint32_t dst, const void* src){
  asm volatile("cp.async.cg.shared.global [%0], [%1], 16;" :: "r"(dst), "l"(src) : "memory");
}
__device__ __forceinline__ void cp_commit(){ asm volatile("cp.async.commit_group;" ::: "memory"); }
template<int N> __device__ __forceinline__ void cp_wait(){ asm volatile("cp.async.wait_group %0;" :: "n"(N) : "memory"); }

__device__ __forceinline__ void ldsm4(uint32_t* r, uint32_t addr){
  asm volatile("ldmatrix.sync.aligned.m8n8.x4.shared.b16 {%0,%1,%2,%3}, [%4];"
    : "=r"(r[0]), "=r"(r[1]), "=r"(r[2]), "=r"(r[3]) : "r"(addr));
}
__device__ __forceinline__ void mma16816(float* c, const uint32_t* a, uint32_t b0, uint32_t b1){
  asm volatile("mma.sync.aligned.m16n8k16.row.col.f32.f16.f16.f32 "
    "{%0,%1,%2,%3}, {%4,%5,%6,%7}, {%8,%9}, {%0,%1,%2,%3};"
    : "+f"(c[0]), "+f"(c[1]), "+f"(c[2]), "+f"(c[3])
    : "r"(a[0]), "r"(a[1]), "r"(a[2]), "r"(a[3]), "r"(b0), "r"(b1));
}

// build 16 A-elements (one z, 16 u) for chunk: t = sum_i x[u*d1+i]*mv[i], hi/lo half2
template<int D1>
__device__ __forceinline__ void build_A(const float* __restrict__ xb,
                                        const float* __restrict__ mvp,
                                        uint32_t sbA, int zi, int uh, int u0){
  float mvv[D1];
  #pragma unroll
  for (int i = 0; i < D1; ++i) mvv[i] = mvp[i];
  #pragma unroll
  for (int s4 = 0; s4 < 4; ++s4){
    int uu = u0 + uh*16 + s4*4;
    float4 fr[D1];
    const float4* p4 = (const float4*)(xb + uu*D1);   // 16B-aligned by construction
    #pragma unroll
    for (int q = 0; q < D1; ++q) fr[q] = p4[q];
    const float* f = (const float*)fr;
    uint32_t o[4];
    #pragma unroll
    for (int t = 0; t < 4; ++t){
      float tv = 0.f;
      #pragma unroll
      for (int i = 0; i < D1; ++i) tv += f[t*D1 + i] * mvv[i];
      __half hi = __float2half_rn(tv);
      __half lo = __float2half_rn(tv - __half2float(hi));
      o[t] = ((uint32_t)__half_as_ushort(lo) << 16) | (uint32_t)__half_as_ushort(hi);
    }
    asm volatile("st.shared.v4.b32 [%0], {%1,%2,%3,%4};"
      :: "r"(sbA + SWZ(zi*128 + uh*64 + s4*16)), "r"(o[0]), "r"(o[1]), "r"(o[2]), "r"(o[3])
      : "memory");
  }
}

__global__ void __launch_bounds__(256, 2) gemm_fused(const float* __restrict__ x,
                                                     const float* __restrict__ y,
                                                     float* __restrict__ out){
  extern __shared__ __align__(1024) char smem[];
  uint32_t sb = smem_u32(smem);
  int tid = threadIdx.x, wid = tid >> 5, lane = tid & 31;

  int sub = blockIdx.x % 9;
  int zt  = blockIdx.x / 9;
  int g   = g_sub_g[sub];
  int kq  = g_sub_kq[sub];
  int z0  = zt * 128;

  int NI = gNI[g], P = gP[g], C = gC[g], nk = gnk[g], obase = gobase[g];
  const __half* pB = (const __half*)(g_W + g*128*640);

  float* ysm = (float*)smem;              // [0, 8K)   transient (aliases A)
  float* cgs = (float*)(smem + 8192);     // [8K, 10.3K) transient
  float* mvs = (float*)(smem + 49152);    // [48K, 57.3K)

  // prologue: issue B0, stage y + cg
  {
    uint32_t stB = sb + 16384u;
    #pragma unroll
    for (int i = 0; i < 4; ++i){
      int idx = tid + i*256;
      int r = idx >> 3, sg = idx & 7;
      cp16(stB + SWZ(r*128 + sg*16), pB + (size_t)r*1280 + sg*8);
    }
    cp_commit();
  }
  for (int idx = tid; idx < 2048; idx += 256) ysm[idx] = y[(size_t)z0*16 + idx];
  for (int idx = tid; idx < 573; idx += 256) cgs[idx] = g_cg[idx];
  __syncthreads();

  // mv[z][j] = sum_j' cg_p[i, j', kq] * y[z, j']   (j = (pl,i) flattened)
  for (int idx = tid; idx < 128*NI; idx += 256){
    int z = idx / NI, j = idx - z*NI;
    int pl = 0;
    #pragma unroll
    for (int q = 1; q < 5; ++q) if (q < P && j >= gmvo[g][q]) pl = q;
    int i = j - gmvo[g][pl];
    int l2v = gl2[g][pl], d2 = 2*l2v + 1;
    const float* cgp = cgs + gcgo[g][pl] + i*d2*nk + kq;
    const float* yp  = ysm + z*16 + c_yoff[l2v];
    float s = 0.f;
    for (int jj = 0; jj < d2; ++jj) s += cgp[jj*nk] * yp[jj];
    mvs[z*18 + j] = s;
  }
  __syncthreads();

  // warp tiling (validated R4/R5)
  int m0 = (wid & 3) * 32;
  int n0 = (wid >> 2) * 64;
  int rA = (lane & 7) + (lane & 8);
  int cAb = (lane >> 4) << 4;
  int rB = (lane & 7) + ((lane >> 4) << 3);
  int cBb = ((lane >> 3) & 1) << 4;

  float acc[2][8][4];
  #pragma unroll
  for (int a = 0; a < 2; ++a)
    #pragma unroll
    for (int b = 0; b < 8; ++b)
      #pragma unroll
      for (int c = 0; c < 4; ++c) acc[a][b][c] = 0.f;

  int zi = tid >> 1, uh = tid & 1;

  for (int c = 0; c < C; ++c){
    if (c + 1 < C){      // issue B_{c+1}
      uint32_t stB = sb + 16384u + (uint32_t)((c + 1) & 1)*16384u;
      int k0 = (c + 1) * 64;
      #pragma unroll
      for (int i = 0; i < 4; ++i){
        int idx = tid + i*256;
        int r = idx >> 3, sg = idx & 7;
        cp16(stB + SWZ(r*128 + sg*16), pB + (size_t)r*1280 + k0 + sg*8);
      }
      cp_commit();
    }

    // build A_c in smem
    {
      int pl = c >> 2;
      int l1v = gl1[g][pl];
      int u0c = (c & 3) * 32;
      const float* xb = x + (size_t)(z0 + zi)*1152 + c_xoff[l1v];
      const float* mvp = mvs + zi*18 + gmvo[g][pl];
      if (l1v == 0)      build_A<1>(xb, mvp, sb, zi, uh, u0c);
      else if (l1v == 1) build_A<3>(xb, mvp, sb, zi, uh, u0c);
      else               build_A<5>(xb, mvp, sb, zi, uh, u0c);
    }

    if (c + 1 < C) cp_wait<1>(); else cp_wait<0>();
    __syncthreads();

    uint32_t stA = sb;
    uint32_t stB = sb + 16384u + (uint32_t)(c & 1)*16384u;
    #pragma unroll
    for (int kk = 0; kk < 4; ++kk){
      int cb = kk*32;
      uint32_t afr[2][4];
      #pragma unroll
      for (int mt = 0; mt < 2; ++mt)
        ldsm4(afr[mt], stA + SWZ((m0 + mt*16 + rA)*128 + cb + cAb));
      uint32_t bfr[4][4];
      #pragma unroll
      for (int bt = 0; bt < 4; ++bt)
        ldsm4(bfr[bt], stB + SWZ((n0 + bt*16 + rB)*128 + cb + cBb));
      #pragma unroll
      for (int mt = 0; mt < 2; ++mt)
        #pragma unroll
        for (int nt = 0; nt < 8; ++nt){
          int bt = nt >> 1, rp = (nt & 1) * 2;
          mma16816(acc[mt][nt], afr[mt], bfr[bt][rp], bfr[bt][rp+1]);
        }
    }
    __syncthreads();
  }

  // epilogue
  float* Csh = (float*)smem;   // [128][132]
  #pragma unroll
  for (int mt = 0; mt < 2; ++mt)
    #pragma unroll
    for (int nt = 0; nt < 8; ++nt){
      int r = m0 + mt*16 + (lane >> 2);
      int cc = n0 + nt*8 + (lane & 3)*2;
      Csh[r*132 + cc]       = acc[mt][nt][0];
      Csh[r*132 + cc + 1]   = acc[mt][nt][1];
      Csh[(r+8)*132 + cc]   = acc[mt][nt][2];
      Csh[(r+8)*132 + cc+1] = acc[mt][nt][3];
    }
  __syncthreads();

  for (int rr = wid; rr < 128; rr += 8){
    const float* src = Csh + rr*132;
    size_t base = (size_t)(z0 + rr)*1152 + obase + kq;
    if (nk == 1){
      float4 v = *(const float4*)(src + lane*4);
      *(float4*)(out + base + lane*4) = v;
    } else {
      #pragma unroll
      for (int j = 0; j < 4; ++j){
        int w = lane + j*32;
        out[base + (size_t)w*nk] = src[w];
      }
    }
  }
}

// ---------------- launch ----------------
extern "C" void kernel_launch(void* const* d_in, const int* in_sizes, int n_in,
                              void* d_out, int out_size){
  const float* x = (const float*)d_in[0];
  const float* y = (const float*)d_in[1];
  const float* w = (const float*)d_in[2];
  float* out = (float*)d_out;
  int n = in_sizes[0] / 1152;   // 65536

  cudaFuncSetAttribute(gemm_fused, cudaFuncAttributeMaxDynamicSharedMemorySize, SMEM_SZ);

  cg_kernel<<<1, 32>>>();
  wprep<<<(3*128*640 + 255)/256, 256>>>(w);
  gemm_fused<<<(n / 128) * 9, 256, SMEM_SZ>>>(x, y, out);
}

// round 7
// speedup vs baseline: 1.1120x; 1.1120x over previous
#include <cuda_runtime.h>
#include <cuda_fp16.h>
#include <cstdint>

typedef unsigned long long ull;
#define NPATH 13
#define SMEM_SZ 131072

// ---------------- static device scratch ----------------
__device__ __align__(256) float g_cg[573];
__device__ __align__(256) __half2 g_T0[65536ull*384];    // (t,t) dup, K'=768
__device__ __align__(256) __half2 g_T1[196608ull*640];   // K'=1280
__device__ __align__(256) __half2 g_T2[327680ull*640];
__device__ __align__(256) __half2 g_W[3*128*640];        // B[n][k] = (wh, wl)
__device__ __align__(256) float g_C1[3ull*65536*128];    // compact io1 output
__device__ __align__(256) float g_C2[5ull*65536*128];    // compact io2 output

__device__ const int c_L1[NPATH]   = {0,0,0,1,1,1,1,1,2,2,2,2,2};
__device__ const int c_L2[NPATH]   = {0,1,2,0,1,1,2,3,0,1,2,2,3};
__device__ const int c_LO[NPATH]   = {0,1,2,1,0,2,1,2,2,1,0,2,1};
__device__ const int c_CGOFF[NPATH]= {0,1,10,35,44,53,98,143,248,273,318,343,468};
__device__ const int c_MSZ[NPATH]  = {1,3,5,9,3,15,9,15,25,15,5,25,15};
__device__ const int c_YOFF[4]     = {0,1,4,9};
__device__ const int c_PB[3][5] = {
  {0,      65536,  163840, 0,      0     },
  {16384,  49152,  98304,  147456, 196608},
  {32768,  81920,  114688, 131072, 180224}
};

// ---------------- CG computation (fp64, ported from reference) ----------------
__device__ double dfact(int n){ double r = 1.0; for (int i = 2; i <= n; ++i) r *= (double)i; return r; }

__device__ double su2_cg(int j1,int m1,int j2,int m2,int j3,int m3){
  if (m3 != m1 + m2) return 0.0;
  int vmin = max(max(-j1 + j2 + m3, -j1 + m1), 0);
  int vmax = min(min(j2 + j3 + m1, j3 - j1 + j2), j3 + m3);
  double C = sqrt((double)(2*j3+1) * dfact(j3+j1-j2) * dfact(j3-j1+j2) * dfact(j1+j2-j3)
                  * dfact(j3+m3) * dfact(j3-m3)
                  / (dfact(j1+j2+j3+1) * dfact(j1-m1) * dfact(j1+m1) * dfact(j2-m2) * dfact(j2+m2)));
  double S = 0.0;
  for (int v = vmin; v <= vmax; ++v){
    double sg = ((v + j2 + m2) & 1) ? -1.0 : 1.0;
    S += sg * dfact(j2+j3+m1-v) * dfact(j1-m1+v)
         / (dfact(v) * dfact(j3-j1+j2-v) * dfact(j3+m3-v) * dfact(v+j1-j2-m3));
  }
  return C * S;
}

__device__ void build_q(int l, double (*qr)[7], double (*qi)[7]){
  for (int a = 0; a < 7; ++a) for (int b = 0; b < 7; ++b){ qr[a][b] = 0.0; qi[a][b] = 0.0; }
  double s = 1.0 / sqrt(2.0);
  for (int m = -l; m < 0; ++m){ qr[l+m][l-m] = s; qi[l+m][l+m] = -s; }
  qr[l][l] = 1.0;
  for (int m = 1; m <= l; ++m){
    double sg = (m & 1) ? -1.0 : 1.0;
    qr[l+m][l+m] = sg * s; qi[l+m][l-m] = sg * s;
  }
  int ph = l & 3;
  if (ph){
    for (int a = 0; a < 2*l+1; ++a) for (int b = 0; b < 2*l+1; ++b){
      double re = qr[a][b], im = qi[a][b];
      if (ph == 1){ qr[a][b] =  im; qi[a][b] = -re; }
      else if (ph == 2){ qr[a][b] = -re; qi[a][b] = -im; }
      else { qr[a][b] = -im; qi[a][b] =  re; }
    }
  }
}

__global__ void cg_kernel(){
  int p = threadIdx.x;
  if (p >= NPATH) return;
  int l1 = c_L1[p], l2 = c_L2[p], l3 = c_LO[p];
  int d1 = 2*l1+1, d2 = 2*l2+1, d3 = 2*l3+1;

  double Ccg[5][7][5];
  for (int a = 0; a < 5; ++a) for (int b = 0; b < 7; ++b) for (int c = 0; c < 5; ++c) Ccg[a][b][c] = 0.0;
  for (int m1 = -l1; m1 <= l1; ++m1)
    for (int m2 = -l2; m2 <= l2; ++m2){
      int m3 = m1 + m2;
      if (m3 >= -l3 && m3 <= l3)
        Ccg[l1+m1][l2+m2][l3+m3] = su2_cg(l1, m1, l2, m2, l3, m3);
    }

  double q1r[7][7], q1i[7][7], q2r[7][7], q2i[7][7], q3r[7][7], q3i[7][7];
  build_q(l1, q1r, q1i); build_q(l2, q2r, q2i); build_q(l3, q3r, q3i);

  double outv[5][7][5];
  double norm2 = 0.0;
  for (int j = 0; j < d1; ++j)
    for (int l = 0; l < d2; ++l)
      for (int m = 0; m < d3; ++m){
        double re = 0.0;
        for (int i = 0; i < d1; ++i){
          double a1r = q1r[i][j], a1i = q1i[i][j];
          if (a1r == 0.0 && a1i == 0.0) continue;
          for (int k = 0; k < d2; ++k){
            double a2r = q2r[k][l], a2i = q2i[k][l];
            if (a2r == 0.0 && a2i == 0.0) continue;
            double ar = a1r*a2r - a1i*a2i;
            double ai = a1r*a2i + a1i*a2r;
            for (int n = 0; n < d3; ++n){
              double c = Ccg[i][k][n];
              if (c == 0.0) continue;
              re += c * (ar*q3r[n][m] - ai*(-q3i[n][m]));
            }
          }
        }
        outv[j][l][m] = re;
        norm2 += re * re;
      }
  double cio = (l3 == 0) ? sqrt(1.0/384.0) : (l3 == 1 ? sqrt(3.0/640.0) : sqrt(5.0/640.0));
  double inv = cio / sqrt(norm2);
  for (int j = 0; j < d1; ++j)
    for (int l = 0; l < d2; ++l)
      for (int m = 0; m < d3; ++m)
        g_cg[c_CGOFF[p] + (j*d2 + l)*d3 + m] = (float)(outv[j][l][m] * inv);
}

// ---------------- weight prep: B[n][k] = (wh, wl) hi/lo split ----------------
__global__ void wprep(const float* __restrict__ w){
  int idx = blockIdx.x * 256 + threadIdx.x;
  if (idx >= 3*128*640) return;
  int g = idx / (128*640);
  int rem = idx - g*128*640;
  int n = rem / 640, k = rem % 640;
  int K = (g == 0) ? 384 : 640;
  float v = 0.f;
  if (k < K) v = w[c_PB[g][k >> 7] + (k & 127)*128 + n];
  __half h = __float2half_rn(v);
  __half l = __float2half_rn(v - __half2float(h));
  g_W[idx] = __halves2half2(h, l);
}

// ---------------- f32x2 helpers ----------------
__device__ __forceinline__ ull pack2(float a, float b){
  ull r; asm("mov.b64 %0, {%1, %2};" : "=l"(r) : "f"(a), "f"(b)); return r;
}
__device__ __forceinline__ void fma2(ull& d, ull a, ull b){
  asm("fma.rn.f32x2 %0, %1, %2, %0;" : "+l"(d) : "l"(a), "l"(b));
}
// convert f32x2 (t_u, t_v) -> store ((h_u,h_u),(h_v,h_v)) as 8B
__device__ __forceinline__ void emit(__half2* p, ull acc){
  float tu, tv;
  asm("mov.b64 {%0, %1}, %2;" : "=f"(tu), "=f"(tv) : "l"(acc));
  uint32_t hp;
  asm("cvt.rn.f16x2.f32 %0, %1, %2;" : "=r"(hp) : "f"(tv), "f"(tu)); // lo=h(tu), hi=h(tv)
  uint32_t lo, hi;
  asm("prmt.b32 %0, %1, %1, 0x1010;" : "=r"(lo) : "r"(hp));
  asm("prmt.b32 %0, %1, %1, 0x3232;" : "=r"(hi) : "r"(hp));
  asm volatile("st.global.v2.b32 [%0], {%1, %2};" :: "l"(p), "r"(lo), "r"(hi) : "memory");
}

// ---------------- T build: u-pair f32x2, single-cvt dup stores ----------------
#define ZB 8
__global__ void __launch_bounds__(256) t_build(const float* __restrict__ x,
                                               const float* __restrict__ y){
  __shared__ float  xs[ZB * 1152];
  __shared__ float  ys[ZB * 16];
  __shared__ float2 Ms2[ZB * 145];   // (m, m) duplicated

  int z0  = blockIdx.x * ZB;
  int tid = threadIdx.x;

  for (int idx = tid; idx < ZB*1152; idx += 256) xs[idx] = x[(size_t)z0*1152 + idx];
  for (int idx = tid; idx < ZB*16;   idx += 256) ys[idx] = y[(size_t)z0*16 + idx];
  __syncthreads();

  for (int idx = tid; idx < ZB*145; idx += 256){
    int zl = idx / 145, e0 = idx % 145;
    int e = e0, p = 0;
    while (e >= c_MSZ[p]){ e -= c_MSZ[p]; ++p; }
    int l2 = c_L2[p], lo = c_LO[p];
    int d2 = 2*l2+1, dlo = 2*lo+1;
    int i = e / dlo, k = e % dlo;
    const float* cg = g_cg + c_CGOFF[p] + (i*d2)*dlo + k;
    const float* yy = ys + zl*16 + c_YOFF[l2];
    float s = 0.f;
    for (int j = 0; j < d2; ++j) s += cg[j*dlo] * yy[j];
    Ms2[zl*145 + e0] = make_float2(s, s);
  }
  __syncthreads();

  int up = tid & 63;     // u-pair: u = 2up, 2up+1
  int zh = tid >> 6;     // 0..3
  for (int zl = zh; zl < ZB; zl += 4){
    const float* xz = xs + zl*1152;
    const ull* M2 = (const ull*)(Ms2 + zl*145);
    size_t z = z0 + zl;

    // pack x pairs (x_u[i], x_v[i])
    ull a0, a1[3], a2[5];
    {
      float2 r = *(const float2*)(xz + 2*up);
      a0 = pack2(r.x, r.y);
      const float2* p = (const float2*)(xz + 128 + 6*up);
      float2 q0 = p[0], q1 = p[1], q2 = p[2];
      a1[0] = pack2(q0.x, q1.y);
      a1[1] = pack2(q0.y, q2.x);
      a1[2] = pack2(q1.x, q2.y);
      const float2* s = (const float2*)(xz + 512 + 10*up);
      float2 s0 = s[0], s1 = s[1], s2 = s[2], s3 = s[3], s4 = s[4];
      a2[0] = pack2(s0.x, s2.y);
      a2[1] = pack2(s0.y, s3.x);
      a2[2] = pack2(s1.x, s3.y);
      a2[3] = pack2(s1.y, s4.x);
      a2[4] = pack2(s2.x, s4.y);
    }

    { // io0: row z, K=384
      __half2* T = g_T0 + z*384 + 2*up;
      ull acc = 0; fma2(acc, a0, M2[0]); emit(T, acc);
      acc = 0;
      #pragma unroll
      for (int i = 0; i < 3; ++i) fma2(acc, a1[i], M2[18 + i]);
      emit(T + 128, acc);
      acc = 0;
      #pragma unroll
      for (int i = 0; i < 5; ++i) fma2(acc, a2[i], M2[100 + i]);
      emit(T + 256, acc);
    }
    #pragma unroll
    for (int k = 0; k < 3; ++k){ // io1: row z*3+k, K=640
      __half2* T = g_T1 + (z*3 + k)*640 + 2*up;
      ull acc = 0; fma2(acc, a0, M2[1 + k]); emit(T, acc);
      acc = 0;
      #pragma unroll
      for (int i = 0; i < 3; ++i) fma2(acc, a1[i], M2[9 + i*3 + k]);
      emit(T + 128, acc);
      acc = 0;
      #pragma unroll
      for (int i = 0; i < 3; ++i) fma2(acc, a1[i], M2[36 + i*3 + k]);
      emit(T + 256, acc);
      acc = 0;
      #pragma unroll
      for (int i = 0; i < 5; ++i) fma2(acc, a2[i], M2[85 + i*3 + k]);
      emit(T + 384, acc);
      acc = 0;
      #pragma unroll
      for (int i = 0; i < 5; ++i) fma2(acc, a2[i], M2[130 + i*3 + k]);
      emit(T + 512, acc);
    }
    #pragma unroll
    for (int k = 0; k < 5; ++k){ // io2: row z*5+k, K=640
      __half2* T = g_T2 + (z*5 + k)*640 + 2*up;
      ull acc = 0; fma2(acc, a0, M2[4 + k]); emit(T, acc);
      acc = 0;
      #pragma unroll
      for (int i = 0; i < 3; ++i) fma2(acc, a1[i], M2[21 + i*5 + k]);
      emit(T + 128, acc);
      acc = 0;
      #pragma unroll
      for (int i = 0; i < 3; ++i) fma2(acc, a1[i], M2[45 + i*5 + k]);
      emit(T + 256, acc);
      acc = 0;
      #pragma unroll
      for (int i = 0; i < 5; ++i) fma2(acc, a2[i], M2[60 + i*5 + k]);
      emit(T + 384, acc);
      acc = 0;
      #pragma unroll
      for (int i = 0; i < 5; ++i) fma2(acc, a2[i], M2[105 + i*5 + k]);
      emit(T + 512, acc);
    }
  }
}

// ---------------- mma.sync GEMM, 4-stage cp.async pipeline ----------------
__device__ __forceinline__ uint32_t smem_u32(const void* p){
  uint32_t a;
  asm("{ .reg .u64 t; cvta.to.shared.u64 t, %1; cvt.u32.u64 %0, t; }" : "=r"(a) : "l"(p));
  return a;
}
#define SWZ(off) ((off) ^ (((off) >> 3) & 0x70))

__device__ __forceinline__ void cp16(uint32_t dst, const void* src){
  asm volatile("cp.async.cg.shared.global [%0], [%1], 16;" :: "r"(dst), "l"(src) : "memory");
}
__device__ __forceinline__ void cp_commit(){ asm volatile("cp.async.commit_group;" ::: "memory"); }
template<int N> __device__ __forceinline__ void cp_wait(){ asm volatile("cp.async.wait_group %0;" :: "n"(N) : "memory"); }

__device__ __forceinline__ void ldsm4(uint32_t* r, uint32_t addr){
  asm volatile("ldmatrix.sync.aligned.m8n8.x4.shared.b16 {%0,%1,%2,%3}, [%4];"
    : "=r"(r[0]), "=r"(r[1]), "=r"(r[2]), "=r"(r[3]) : "r"(addr));
}
__device__ __forceinline__ void mma16816(float* c, const uint32_t* a, uint32_t b0, uint32_t b1){
  asm volatile("mma.sync.aligned.m16n8k16.row.col.f32.f16.f16.f32 "
    "{%0,%1,%2,%3}, {%4,%5,%6,%7}, {%8,%9}, {%0,%1,%2,%3};"
    : "+f"(c[0]), "+f"(c[1]), "+f"(c[2]), "+f"(c[3])
    : "r"(a[0]), "r"(a[1]), "r"(a[2]), "r"(a[3]), "r"(b0), "r"(b1));
}

__global__ void __launch_bounds__(256, 1) gemm_mma(float* __restrict__ out,
                                                   int io, int Kp, int nk){
  extern __shared__ __align__(1024) char smem[];
  uint32_t sb = smem_u32(smem);
  int tid = threadIdx.x, wid = tid >> 5, lane = tid & 31;

  const __half* pA = (io == 0) ? (const __half*)g_T0 : (io == 1) ? (const __half*)g_T1 : (const __half*)g_T2;
  const __half* pB = (const __half*)(g_W + io*128*640);
  float* gC = (io == 1) ? g_C1 : g_C2;
  size_t strideA = (io == 0) ? 768 : 1280;
  size_t R0 = (size_t)blockIdx.x * 128;
  int C = Kp / 64;

  int m0 = (wid & 3) * 32;
  int n0 = (wid >> 2) * 64;

  float acc[2][8][4];
  #pragma unroll
  for (int a = 0; a < 2; ++a)
    #pragma unroll
    for (int b = 0; b < 8; ++b)
      #pragma unroll
      for (int c = 0; c < 4; ++c) acc[a][b][c] = 0.f;

  int rA = (lane & 7) + (lane & 8);
  int cAb = (lane >> 4) << 4;
  int rB = (lane & 7) + ((lane >> 4) << 3);
  int cBb = ((lane >> 3) & 1) << 4;

  #define ISSUE(c_) do{                                                     \
    int s_ = (c_) & 3;                                                      \
    uint32_t stA_ = sb + s_*32768u, stB_ = stA_ + 16384u;                   \
    int k0_ = (c_) * 64;                                                    \
    _Pragma("unroll")                                                       \
    for (int i_ = 0; i_ < 4; ++i_){                                         \
      int idx_ = tid + i_*256;                                              \
      int r_ = idx_ >> 3, sg_ = idx_ & 7;                                   \
      cp16(stA_ + SWZ(r_*128 + sg_*16), pA + (R0 + r_)*strideA + k0_ + sg_*8); \
      cp16(stB_ + SWZ(r_*128 + sg_*16), pB + (size_t)r_*1280 + k0_ + sg_*8);   \
    }                                                                       \
    cp_commit();                                                            \
  }while(0)

  ISSUE(0); ISSUE(1); ISSUE(2);

  for (int c = 0; c < C; ++c){
    __syncthreads();
    if (c + 3 < C){ ISSUE(c + 3); cp_wait<3>(); }
    else {
      int rem = C - 1 - c;
      if (rem >= 2) cp_wait<2>(); else if (rem == 1) cp_wait<1>(); else cp_wait<0>();
    }
    __syncthreads();

    uint32_t stA = sb + (uint32_t)(c & 3)*32768u;
    uint32_t stB = stA + 16384u;
    #pragma unroll
    for (int kk = 0; kk < 4; ++kk){
      int cb = kk*32;
      uint32_t afr[2][4];
      #pragma unroll
      for (int mt = 0; mt < 2; ++mt)
        ldsm4(afr[mt], stA + SWZ((m0 + mt*16 + rA)*128 + cb + cAb));
      uint32_t bfr[4][4];
      #pragma unroll
      for (int bt = 0; bt < 4; ++bt)
        ldsm4(bfr[bt], stB + SWZ((n0 + bt*16 + rB)*128 + cb + cBb));
      #pragma unroll
      for (int mt = 0; mt < 2; ++mt)
        #pragma unroll
        for (int nt = 0; nt < 8; ++nt){
          int bt = nt >> 1, rp = (nt & 1) * 2;
          mma16816(acc[mt][nt], afr[mt], bfr[bt][rp], bfr[bt][rp+1]);
        }
    }
  }
  __syncthreads();

  // epilogue: accumulators -> smem -> fully-coalesced float4 stores
  float* Csh = (float*)smem;   // [128][132]
  #pragma unroll
  for (int mt = 0; mt < 2; ++mt)
    #pragma unroll
    for (int nt = 0; nt < 8; ++nt){
      int r = m0 + mt*16 + (lane >> 2);
      int cc = n0 + nt*8 + (lane & 3)*2;
      Csh[r*132 + cc]       = acc[mt][nt][0];
      Csh[r*132 + cc + 1]   = acc[mt][nt][1];
      Csh[(r+8)*132 + cc]   = acc[mt][nt][2];
      Csh[(r+8)*132 + cc+1] = acc[mt][nt][3];
    }
  __syncthreads();

  for (int rr = wid; rr < 128; rr += 8){
    const float* src = Csh + rr*132;
    int rg = (int)R0 + rr;
    float4 v = *(const float4*)(src + lane*4);
    if (nk == 1){
      *(float4*)(out + (size_t)rg*1152 + lane*4) = v;
    } else {
      int z = rg / nk, kq = rg - z*nk;
      *(float4*)(gC + ((size_t)kq*65536 + z)*128 + lane*4) = v;
    }
  }
  #undef ISSUE
}

// ---------------- interleave: compact C1/C2 -> e3nn output layout ----------------
__global__ void __launch_bounds__(256) interleave(float* __restrict__ out){
  __shared__ float sh[8*1024];
  int z0 = blockIdx.x * 8;
  int tid = threadIdx.x;

  for (int idx = tid; idx < 3072; idx += 256){
    int w = idx & 127, r = idx >> 7;
    int kq = r >> 3, zr = r & 7;
    sh[zr*1024 + w*3 + kq] = g_C1[((size_t)kq*65536 + z0 + zr)*128 + w];
  }
  for (int idx = tid; idx < 5120; idx += 256){
    int w = idx & 127, r = idx >> 7;
    int kq = r >> 3, zr = r & 7;
    sh[zr*1024 + 384 + w*5 + kq] = g_C2[((size_t)kq*65536 + z0 + zr)*128 + w];
  }
  __syncthreads();

  for (int idx = tid; idx < 2048; idx += 256){
    int zr = idx >> 8, c4 = idx & 255;
    *(float4*)(out + (size_t)(z0 + zr)*1152 + 128 + c4*4) =
        *(const float4*)(sh + zr*1024 + c4*4);
  }
}

// ---------------- launch ----------------
extern "C" void kernel_launch(void* const* d_in, const int* in_sizes, int n_in,
                              void* d_out, int out_size){
  const float* x = (const float*)d_in[0];
  const float* y = (const float*)d_in[1];
  const float* w = (const float*)d_in[2];
  float* out = (float*)d_out;
  int n = in_sizes[0] / 1152;   // 65536

  cudaFuncSetAttribute(gemm_mma, cudaFuncAttributeMaxDynamicSharedMemorySize, SMEM_SZ);

  cg_kernel<<<1, 32>>>();
  wprep<<<(3*128*640 + 255)/256, 256>>>(w);
  t_build<<<n / ZB, 256>>>(x, y);
  gemm_mma<<<(n / 128)    , 256, SMEM_SZ>>>(out, 0, 768,  1);
  gemm_mma<<<(n / 128) * 3, 256, SMEM_SZ>>>(out, 1, 1280, 3);
  gemm_mma<<<(n / 128) * 5, 256, SMEM_SZ>>>(out, 2, 1280, 5);
  interleave<<<n / 8, 256>>>(out);
}